// round 4
// baseline (speedup 1.0000x reference)
#include <cuda_runtime.h>
#include <cstdint>

#define NT   8192
#define DIMD 2048
#define HID  1408
#define NE   8
#define CAP  (NT/NE)   // 1024

#define BM 128
#define BN 64
#define BK 32
#define THREADS 256
#define NSTAGE 3

// Scratch: tf32-rounded copies of inputs + intermediate h (rounded in epilogue)
__device__ float g_xr[(size_t)NT * DIMD];
__device__ float g_w1r[(size_t)NE * HID * DIMD];
__device__ float g_w3r[(size_t)NE * HID * DIMD];
__device__ float g_w2r[(size_t)NE * DIMD * HID];
__device__ float g_h[(size_t)NT * HID];

__device__ __forceinline__ uint32_t smem_u32(const void* p) {
    uint32_t a;
    asm("{ .reg .u64 t; cvta.to.shared.u64 t, %1; cvt.u32.u64 %0, t; }" : "=r"(a) : "l"(p));
    return a;
}
__device__ __forceinline__ uint32_t f2tf(float f) {
    uint32_t u;
    asm("cvt.rna.tf32.f32 %0, %1;" : "=r"(u) : "f"(f));
    return u;
}

#define CP16(s, g)   asm volatile("cp.async.cg.shared.global [%0], [%1], 16;" :: "r"(s), "l"(g))
#define CP_COMMIT()  asm volatile("cp.async.commit_group;" ::: "memory")
#define CP_WAIT1()   asm volatile("cp.async.wait_group 1;" ::: "memory")
#define CP_WAIT0()   asm volatile("cp.async.wait_group 0;" ::: "memory")

// word index inside a [rows][32] fp32 tile, XOR-swizzled (verified in R1/R3)
__device__ __forceinline__ int sidx(int r, int c) {
    return r * BK + ((((c >> 2) ^ (r & 7))) << 2) + (c & 3);
}

__device__ __forceinline__ void mma8(float* d, const uint32_t* a, const uint32_t* b) {
    asm volatile(
        "mma.sync.aligned.m16n8k8.row.col.f32.tf32.tf32.f32 "
        "{%0,%1,%2,%3}, {%4,%5,%6,%7}, {%8,%9}, {%0,%1,%2,%3};"
        : "+f"(d[0]), "+f"(d[1]), "+f"(d[2]), "+f"(d[3])
        : "r"(a[0]), "r"(a[1]), "r"(a[2]), "r"(a[3]), "r"(b[0]), "r"(b[1]));
}

__device__ __forceinline__ float silu(float v) { return v / (1.f + __expf(-v)); }

// ---------------------------------------------------------------------------
// Pre-round: fp32 -> tf32(RNA) bit pattern stored as fp32
// ---------------------------------------------------------------------------
__global__ void round_tf32(const float4* __restrict__ src, float4* __restrict__ dst, int n4) {
    int i = blockIdx.x * blockDim.x + threadIdx.x;
    int stride = gridDim.x * blockDim.x;
    for (; i < n4; i += stride) {
        float4 v = src[i];
        float4 o;
        o.x = __uint_as_float(f2tf(v.x));
        o.y = __uint_as_float(f2tf(v.y));
        o.z = __uint_as_float(f2tf(v.z));
        o.w = __uint_as_float(f2tf(v.w));
        dst[i] = o;
    }
}

// ---------------------------------------------------------------------------
// Pass 1: h = silu(x@w1^T) * (x@w3^T)
// grid (CAP/BM=8, HID/BN=22, NE) -- m fastest for weight-tile L2 sharing
// smem: 3 stages x (128 x-rows + 64 w1 + 64 w3) x 128B = 3 x 32KB
// K-permutation: MMA col tg <- stored col 2tg, tg+4 <- 2tg+1 (LDS.64 pairs)
// ---------------------------------------------------------------------------
__global__ void __launch_bounds__(THREADS, 2) moe_up(
    const int* __restrict__ cnts)
{
    extern __shared__ uint32_t sm[];
    const uint32_t sb = smem_u32(sm);
    const int tid = threadIdx.x, warp = tid >> 5, lane = tid & 31;
    const int e = blockIdx.z, m0 = blockIdx.x * BM, n0 = blockIdx.y * BN;

    int start = 0;
#pragma unroll
    for (int j = 0; j < NE; j++) { int c = cnts[j]; if (j < e) start += c; }
    const int start_cl = min(start, NT - CAP);

    const float* xg  = g_xr  + (size_t)(start_cl + m0) * DIMD;
    const float* w1g = g_w1r + (size_t)e * HID * DIMD + (size_t)n0 * DIMD;
    const float* w3g = g_w3r + (size_t)e * HID * DIMD + (size_t)n0 * DIMD;

    const int wm = warp >> 1, wn = warp & 1;
    const int g = lane >> 2, tg = lane & 3;

    float acc1[2][4][4], acc3[2][4][4];
#pragma unroll
    for (int i = 0; i < 2; i++)
#pragma unroll
        for (int j = 0; j < 4; j++)
#pragma unroll
            for (int k = 0; k < 4; k++) { acc1[i][j][k] = 0.f; acc3[i][j][k] = 0.f; }

    // 256 rows (128 x | 64 w1 | 64 w3) x 8 chunks = 2048 / 256 thr = 8 each
    auto load_stage = [&](int c, int buf) {
        const uint32_t base = sb + buf * 32768;
        const int koff = c * BK;
#pragma unroll
        for (int j = 0; j < 8; j++) {
            int id = tid + j * THREADS;
            int row = id >> 3, k4 = id & 7;
            uint32_t sa = base + row * 128 + ((k4 ^ (row & 7)) << 4);
            const float* gp;
            if (row < 128)      gp = xg  + (size_t)row * DIMD + koff + k4 * 4;
            else if (row < 192) gp = w1g + (size_t)(row - 128) * DIMD + koff + k4 * 4;
            else                gp = w3g + (size_t)(row - 192) * DIMD + koff + k4 * 4;
            CP16(sa, gp);
        }
        CP_COMMIT();
    };

    load_stage(0, 0);
    load_stage(1, 1);

    const int KIT = DIMD / BK;   // 64
    for (int c = 0; c < KIT; c++) {
        const int s = c % NSTAGE;
        if (c + 1 < KIT) { CP_WAIT1(); } else { CP_WAIT0(); }
        __syncthreads();
        if (c + 2 < KIT) load_stage(c + 2, (c + 2) % NSTAGE);
        const uint32_t* cx = sm + s * 8192;
        const uint32_t* c1 = sm + s * 8192 + 4096;
        const uint32_t* c3 = sm + s * 8192 + 6144;
#pragma unroll
        for (int kk = 0; kk < 4; kk++) {
            uint32_t af[2][4], b1f[4][2], b3f[4][2];
            const int c0 = kk * 8 + tg * 2;   // K-permuted pair base
#pragma unroll
            for (int mt = 0; mt < 2; mt++) {
                int r = wm * 32 + mt * 16 + g;
                uint2 p = *(const uint2*)&cx[sidx(r,     c0)];
                uint2 q = *(const uint2*)&cx[sidx(r + 8, c0)];
                af[mt][0] = p.x; af[mt][1] = q.x; af[mt][2] = p.y; af[mt][3] = q.y;
            }
#pragma unroll
            for (int nt = 0; nt < 4; nt++) {
                int rn = wn * 32 + nt * 8 + g;
                uint2 b1 = *(const uint2*)&c1[sidx(rn, c0)];
                uint2 b3 = *(const uint2*)&c3[sidx(rn, c0)];
                b1f[nt][0] = b1.x; b1f[nt][1] = b1.y;
                b3f[nt][0] = b3.x; b3f[nt][1] = b3.y;
            }
#pragma unroll
            for (int mt = 0; mt < 2; mt++)
#pragma unroll
                for (int nt = 0; nt < 4; nt++) {
                    mma8(acc1[mt][nt], af[mt], b1f[nt]);
                    mma8(acc3[mt][nt], af[mt], b3f[nt]);
                }
        }
    }

    // Epilogue: h = round_tf32(silu(a1) * a3)
    float* hg = g_h + (size_t)(e * CAP + m0) * HID + n0;
#pragma unroll
    for (int mt = 0; mt < 2; mt++)
#pragma unroll
        for (int nt = 0; nt < 4; nt++)
#pragma unroll
            for (int half = 0; half < 2; half++) {
                int r  = wm * 32 + mt * 16 + g + half * 8;
                int cb = wn * 32 + nt * 8 + tg * 2;
                float v1a = acc1[mt][nt][half * 2 + 0];
                float v1b = acc1[mt][nt][half * 2 + 1];
                float v3a = acc3[mt][nt][half * 2 + 0];
                float v3b = acc3[mt][nt][half * 2 + 1];
                float2 o;
                o.x = __uint_as_float(f2tf(silu(v1a) * v3a));
                o.y = __uint_as_float(f2tf(silu(v1b) * v3b));
                *(float2*)(hg + (size_t)r * HID + cb) = o;
            }
}

// ---------------------------------------------------------------------------
// Pass 2: out = h @ w2^T, masked scatter
// grid (CAP/BM=8, DIMD/BN=32, NE), smem 3 x 24KB
// ---------------------------------------------------------------------------
__global__ void __launch_bounds__(THREADS, 3) moe_down(
    const int* __restrict__ cnts, float* __restrict__ out)
{
    extern __shared__ uint32_t sm[];
    const uint32_t sb = smem_u32(sm);
    const int tid = threadIdx.x, warp = tid >> 5, lane = tid & 31;
    const int e = blockIdx.z, m0 = blockIdx.x * BM, n0 = blockIdx.y * BN;

    int start = 0, cnt = 0;
#pragma unroll
    for (int j = 0; j < NE; j++) {
        int c = cnts[j];
        if (j < e) start += c;
        if (j == e) cnt = c;
    }

    const float* hg  = g_h + (size_t)(e * CAP + m0) * HID;
    const float* w2g = g_w2r + (size_t)e * DIMD * HID + (size_t)n0 * HID;

    const int wm = warp >> 1, wn = warp & 1;
    const int g = lane >> 2, tg = lane & 3;

    float acc[2][4][4];
#pragma unroll
    for (int i = 0; i < 2; i++)
#pragma unroll
        for (int j = 0; j < 4; j++)
#pragma unroll
            for (int k = 0; k < 4; k++) acc[i][j][k] = 0.f;

    // 192 rows (128 h | 64 w2) x 8 chunks = 1536 / 256 = 6 each
    auto load_stage = [&](int c, int buf) {
        const uint32_t base = sb + buf * 24576;
        const int koff = c * BK;
#pragma unroll
        for (int j = 0; j < 6; j++) {
            int id = tid + j * THREADS;
            int row = id >> 3, k4 = id & 7;
            uint32_t sa = base + row * 128 + ((k4 ^ (row & 7)) << 4);
            const float* gp;
            if (row < 128) gp = hg  + (size_t)row * HID + koff + k4 * 4;
            else           gp = w2g + (size_t)(row - 128) * HID + koff + k4 * 4;
            CP16(sa, gp);
        }
        CP_COMMIT();
    };

    load_stage(0, 0);
    load_stage(1, 1);

    const int KIT = HID / BK;   // 44
    for (int c = 0; c < KIT; c++) {
        const int s = c % NSTAGE;
        if (c + 1 < KIT) { CP_WAIT1(); } else { CP_WAIT0(); }
        __syncthreads();
        if (c + 2 < KIT) load_stage(c + 2, (c + 2) % NSTAGE);
        const uint32_t* cx = sm + s * 6144;
        const uint32_t* c2 = sm + s * 6144 + 4096;
#pragma unroll
        for (int kk = 0; kk < 4; kk++) {
            uint32_t af[2][4], bf[4][2];
            const int c0 = kk * 8 + tg * 2;
#pragma unroll
            for (int mt = 0; mt < 2; mt++) {
                int r = wm * 32 + mt * 16 + g;
                uint2 p = *(const uint2*)&cx[sidx(r,     c0)];
                uint2 q = *(const uint2*)&cx[sidx(r + 8, c0)];
                af[mt][0] = p.x; af[mt][1] = q.x; af[mt][2] = p.y; af[mt][3] = q.y;
            }
#pragma unroll
            for (int nt = 0; nt < 4; nt++) {
                int rn = wn * 32 + nt * 8 + g;
                uint2 b = *(const uint2*)&c2[sidx(rn, c0)];
                bf[nt][0] = b.x; bf[nt][1] = b.y;
            }
#pragma unroll
            for (int mt = 0; mt < 2; mt++)
#pragma unroll
                for (int nt = 0; nt < 4; nt++)
                    mma8(acc[mt][nt], af[mt], bf[nt]);
        }
    }

#pragma unroll
    for (int mt = 0; mt < 2; mt++)
#pragma unroll
        for (int nt = 0; nt < 4; nt++)
#pragma unroll
            for (int half = 0; half < 2; half++) {
                int r = wm * 32 + mt * 16 + g + half * 8;
                int i = m0 + r;
                if (i < cnt) {
                    int pos = min(start + i, NT - 1);
                    int cb  = n0 + wn * 32 + nt * 8 + tg * 2;
                    float2 o;
                    o.x = acc[mt][nt][half * 2 + 0];
                    o.y = acc[mt][nt][half * 2 + 1];
                    *(float2*)(out + (size_t)pos * DIMD + cb) = o;
                }
            }
}

__global__ void zero_out_kernel(float4* o, int n4) {
    int i = blockIdx.x * blockDim.x + threadIdx.x;
    if (i < n4) o[i] = make_float4(0.f, 0.f, 0.f, 0.f);
}

extern "C" void kernel_launch(void* const* d_in, const int* in_sizes, int n_in,
                              void* d_out, int out_size) {
    (void)in_sizes; (void)n_in; (void)out_size;
    const float* x    = (const float*)d_in[0];
    const int*   cnts = (const int*)d_in[1];
    const float* w1   = (const float*)d_in[2];
    const float* w2   = (const float*)d_in[3];
    const float* w3   = (const float*)d_in[4];
    float* out = (float*)d_out;

    float *xr, *w1r, *w2r, *w3r;
    cudaGetSymbolAddress((void**)&xr,  g_xr);
    cudaGetSymbolAddress((void**)&w1r, g_w1r);
    cudaGetSymbolAddress((void**)&w2r, g_w2r);
    cudaGetSymbolAddress((void**)&w3r, g_w3r);

    cudaFuncSetAttribute(moe_up,   cudaFuncAttributeMaxDynamicSharedMemorySize, NSTAGE * 32768);
    cudaFuncSetAttribute(moe_down, cudaFuncAttributeMaxDynamicSharedMemorySize, NSTAGE * 24576);

    const int nx  = NT * DIMD / 4;
    const int nw  = NE * HID * DIMD / 4;
    round_tf32<<<592, 256>>>((const float4*)x,  (float4*)xr,  nx);
    round_tf32<<<592, 256>>>((const float4*)w1, (float4*)w1r, nw);
    round_tf32<<<592, 256>>>((const float4*)w2, (float4*)w2r, nw);
    round_tf32<<<592, 256>>>((const float4*)w3, (float4*)w3r, nw);

    const int n4 = NT * DIMD / 4;
    zero_out_kernel<<<(n4 + 255) / 256, 256>>>((float4*)out, n4);

    moe_up<<<dim3(CAP / BM, HID / BN, NE), THREADS, NSTAGE * 32768>>>(cnts);
    moe_down<<<dim3(CAP / BM, DIMD / BN, NE), THREADS, NSTAGE * 24576>>>(cnts, out);
}

// round 5
// speedup vs baseline: 2.7369x; 2.7369x over previous
#include <cuda_runtime.h>
#include <cuda_fp16.h>
#include <cstdint>

#define NT   8192
#define DIMD 2048
#define HID  1408
#define NE   8
#define CAP  (NT/NE)   // 1024

#define BM 128
#define BN 64
#define BK2 64         // fp16 K-elems per stage (128B rows)
#define THREADS 256
#define NSTAGE 3

// fp16 copies of inputs + fp16 intermediate h
__device__ __half g_xh[(size_t)NT * DIMD];
__device__ __half g_w1h[(size_t)NE * HID * DIMD];
__device__ __half g_w3h[(size_t)NE * HID * DIMD];
__device__ __half g_w2h[(size_t)NE * DIMD * HID];
__device__ __half g_h[(size_t)NT * HID];

__device__ __forceinline__ uint32_t smem_u32(const void* p) {
    uint32_t a;
    asm("{ .reg .u64 t; cvta.to.shared.u64 t, %1; cvt.u32.u64 %0, t; }" : "=r"(a) : "l"(p));
    return a;
}

#define CP16(s, g)   asm volatile("cp.async.cg.shared.global [%0], [%1], 16;" :: "r"(s), "l"(g))
#define CP_COMMIT()  asm volatile("cp.async.commit_group;" ::: "memory")
#define CP_WAIT1()   asm volatile("cp.async.wait_group 1;" ::: "memory")
#define CP_WAIT0()   asm volatile("cp.async.wait_group 0;" ::: "memory")

#define LDSM4(r0, r1, r2, r3, a) \
    asm volatile("ldmatrix.sync.aligned.m8n8.x4.shared.b16 {%0,%1,%2,%3}, [%4];" \
        : "=r"(r0), "=r"(r1), "=r"(r2), "=r"(r3) : "r"(a))

__device__ __forceinline__ void mma16(float* d, const uint32_t* a, const uint32_t* b) {
    asm volatile(
        "mma.sync.aligned.m16n8k16.row.col.f32.f16.f16.f32 "
        "{%0,%1,%2,%3}, {%4,%5,%6,%7}, {%8,%9}, {%0,%1,%2,%3};"
        : "+f"(d[0]), "+f"(d[1]), "+f"(d[2]), "+f"(d[3])
        : "r"(a[0]), "r"(a[1]), "r"(a[2]), "r"(a[3]), "r"(b[0]), "r"(b[1]));
}

__device__ __forceinline__ float silu(float v) { return v / (1.f + __expf(-v)); }

// ---------------------------------------------------------------------------
// fp32 -> fp16 convert (RN)
// ---------------------------------------------------------------------------
__global__ void f2h_kernel(const float4* __restrict__ src, uint2* __restrict__ dst, int n4) {
    int i = blockIdx.x * blockDim.x + threadIdx.x;
    int stride = gridDim.x * blockDim.x;
    for (; i < n4; i += stride) {
        float4 v = src[i];
        __half2 lo = __floats2half2_rn(v.x, v.y);
        __half2 hi = __floats2half2_rn(v.z, v.w);
        uint2 o;
        o.x = *(const uint32_t*)&lo;
        o.y = *(const uint32_t*)&hi;
        dst[i] = o;
    }
}

// ---------------------------------------------------------------------------
// Pass 1: h = silu(x@w1^T) * (x@w3^T)   [fp16 in, fp32 acc, fp16 h out]
// grid (CAP/BM=8, HID/BN=22, NE); smem 3 x 32KB (x 16KB | w1 8KB | w3 8KB)
// ---------------------------------------------------------------------------
__global__ void __launch_bounds__(THREADS, 2) moe_up(
    const int* __restrict__ cnts)
{
    extern __shared__ char smc[];
    const uint32_t sb = smem_u32(smc);
    const int tid = threadIdx.x, warp = tid >> 5, lane = tid & 31;
    const int e = blockIdx.z, m0 = blockIdx.x * BM, n0 = blockIdx.y * BN;

    int start = 0;
#pragma unroll
    for (int j = 0; j < NE; j++) { int c = cnts[j]; if (j < e) start += c; }
    const int start_cl = min(start, NT - CAP);

    const __half* xg  = g_xh  + (size_t)(start_cl + m0) * DIMD;
    const __half* w1g = g_w1h + (size_t)e * HID * DIMD + (size_t)n0 * DIMD;
    const __half* w3g = g_w3h + (size_t)e * HID * DIMD + (size_t)n0 * DIMD;

    const int wm = warp >> 1, wn = warp & 1;   // 4 m-warps x 2 n-warps
    const int g = lane >> 2, tg = lane & 3;

    float acc1[2][4][4], acc3[2][4][4];
#pragma unroll
    for (int i = 0; i < 2; i++)
#pragma unroll
        for (int j = 0; j < 4; j++)
#pragma unroll
            for (int k = 0; k < 4; k++) { acc1[i][j][k] = 0.f; acc3[i][j][k] = 0.f; }

    // stage = 256 rows x 128B; 2048 16B-chunks / 256 thr = 8 each
    auto load_stage = [&](int c, int buf) {
        const uint32_t base = sb + buf * 32768;
        const int koff = c * BK2;
#pragma unroll
        for (int j = 0; j < 8; j++) {
            int id = tid + j * THREADS;
            int row = id >> 3, k4 = id & 7;
            uint32_t sa = base + row * 128 + ((k4 ^ (row & 7)) << 4);
            const __half* gp;
            if (row < 128)      gp = xg  + (size_t)row * DIMD + koff + k4 * 8;
            else if (row < 192) gp = w1g + (size_t)(row - 128) * DIMD + koff + k4 * 8;
            else                gp = w3g + (size_t)(row - 192) * DIMD + koff + k4 * 8;
            CP16(sa, gp);
        }
        CP_COMMIT();
    };

    load_stage(0, 0);
    load_stage(1, 1);

    // ldmatrix lane addressing (computed once)
    const int a_r = (lane & 7) + ((lane >> 3) & 1) * 8;   // row-within-16
    const int a_c = (lane >> 4);                          // k8-chunk select
    const int b_r = (lane & 7) + ((lane >> 4) & 1) * 8;
    const int b_c = ((lane >> 3) & 1);

    const int KIT = DIMD / BK2;   // 32
    for (int c = 0; c < KIT; c++) {
        const int s = c % NSTAGE;
        if (c + 1 < KIT) { CP_WAIT1(); } else { CP_WAIT0(); }
        __syncthreads();
        const uint32_t xb = sb + s * 32768;
        const uint32_t w1b = xb + 16384;
        const uint32_t w3b = xb + 24576;
#pragma unroll
        for (int kk = 0; kk < 4; kk++) {
            uint32_t a[2][4], b1[2][4], b3[2][4];
#pragma unroll
            for (int mt = 0; mt < 2; mt++) {
                int lr = wm * 32 + mt * 16 + a_r;
                int lc = 2 * kk + a_c;
                uint32_t sa = xb + lr * 128 + ((lc ^ (lr & 7)) << 4);
                LDSM4(a[mt][0], a[mt][1], a[mt][2], a[mt][3], sa);
            }
#pragma unroll
            for (int nt = 0; nt < 2; nt++) {
                int br = wn * 32 + nt * 16 + b_r;
                int bc = 2 * kk + b_c;
                uint32_t sw = ((bc ^ (br & 7)) << 4);
                uint32_t s1 = w1b + br * 128 + sw;
                uint32_t s3 = w3b + br * 128 + sw;
                LDSM4(b1[nt][0], b1[nt][1], b1[nt][2], b1[nt][3], s1);
                LDSM4(b3[nt][0], b3[nt][1], b3[nt][2], b3[nt][3], s3);
            }
#pragma unroll
            for (int mt = 0; mt < 2; mt++)
#pragma unroll
                for (int nt = 0; nt < 2; nt++)
#pragma unroll
                    for (int hf = 0; hf < 2; hf++) {
                        mma16(acc1[mt][nt * 2 + hf], a[mt], &b1[nt][hf * 2]);
                        mma16(acc3[mt][nt * 2 + hf], a[mt], &b3[nt][hf * 2]);
                    }
        }
        __syncthreads();
        if (c + 2 < KIT) load_stage(c + 2, (c + 2) % NSTAGE);
    }

    // Epilogue: h = fp16(silu(a1) * a3)
    __half* hg = g_h + (size_t)(e * CAP + m0) * HID + n0;
#pragma unroll
    for (int mt = 0; mt < 2; mt++)
#pragma unroll
        for (int nf = 0; nf < 4; nf++)
#pragma unroll
            for (int hf = 0; hf < 2; hf++) {
                int r  = wm * 32 + mt * 16 + g + hf * 8;
                int cb = wn * 32 + nf * 8 + tg * 2;
                float v1a = acc1[mt][nf][hf * 2 + 0];
                float v1b = acc1[mt][nf][hf * 2 + 1];
                float v3a = acc3[mt][nf][hf * 2 + 0];
                float v3b = acc3[mt][nf][hf * 2 + 1];
                __half2 o = __floats2half2_rn(silu(v1a) * v3a, silu(v1b) * v3b);
                *(uint32_t*)(hg + (size_t)r * HID + cb) = *(const uint32_t*)&o;
            }
}

// ---------------------------------------------------------------------------
// Pass 2: out = h @ w2^T (fp32 out, masked scatter)
// grid (CAP/BM=8, DIMD/BN=32, NE); smem 3 x 24KB (h 16KB | w2 8KB)
// ---------------------------------------------------------------------------
__global__ void __launch_bounds__(THREADS, 2) moe_down(
    const int* __restrict__ cnts, float* __restrict__ out)
{
    extern __shared__ char smc[];
    const uint32_t sb = smem_u32(smc);
    const int tid = threadIdx.x, warp = tid >> 5, lane = tid & 31;
    const int e = blockIdx.z, m0 = blockIdx.x * BM, n0 = blockIdx.y * BN;

    int start = 0, cnt = 0;
#pragma unroll
    for (int j = 0; j < NE; j++) {
        int c = cnts[j];
        if (j < e) start += c;
        if (j == e) cnt = c;
    }

    const __half* hg  = g_h   + (size_t)(e * CAP + m0) * HID;
    const __half* w2g = g_w2h + (size_t)e * DIMD * HID + (size_t)n0 * HID;

    const int wm = warp >> 1, wn = warp & 1;
    const int g = lane >> 2, tg = lane & 3;

    float acc[2][4][4];
#pragma unroll
    for (int i = 0; i < 2; i++)
#pragma unroll
        for (int j = 0; j < 4; j++)
#pragma unroll
            for (int k = 0; k < 4; k++) acc[i][j][k] = 0.f;

    // stage = 192 rows x 128B; 1536 chunks / 256 = 6 each
    auto load_stage = [&](int c, int buf) {
        const uint32_t base = sb + buf * 24576;
        const int koff = c * BK2;
#pragma unroll
        for (int j = 0; j < 6; j++) {
            int id = tid + j * THREADS;
            int row = id >> 3, k4 = id & 7;
            uint32_t sa = base + row * 128 + ((k4 ^ (row & 7)) << 4);
            const __half* gp;
            if (row < 128) gp = hg  + (size_t)row * HID + koff + k4 * 8;
            else           gp = w2g + (size_t)(row - 128) * HID + koff + k4 * 8;
            CP16(sa, gp);
        }
        CP_COMMIT();
    };

    load_stage(0, 0);
    load_stage(1, 1);

    const int a_r = (lane & 7) + ((lane >> 3) & 1) * 8;
    const int a_c = (lane >> 4);
    const int b_r = (lane & 7) + ((lane >> 4) & 1) * 8;
    const int b_c = ((lane >> 3) & 1);

    const int KIT = HID / BK2;   // 22
    for (int c = 0; c < KIT; c++) {
        const int s = c % NSTAGE;
        if (c + 1 < KIT) { CP_WAIT1(); } else { CP_WAIT0(); }
        __syncthreads();
        const uint32_t xb = sb + s * 24576;
        const uint32_t w2b = xb + 16384;
#pragma unroll
        for (int kk = 0; kk < 4; kk++) {
            uint32_t a[2][4], b2[2][4];
#pragma unroll
            for (int mt = 0; mt < 2; mt++) {
                int lr = wm * 32 + mt * 16 + a_r;
                int lc = 2 * kk + a_c;
                uint32_t sa = xb + lr * 128 + ((lc ^ (lr & 7)) << 4);
                LDSM4(a[mt][0], a[mt][1], a[mt][2], a[mt][3], sa);
            }
#pragma unroll
            for (int nt = 0; nt < 2; nt++) {
                int br = wn * 32 + nt * 16 + b_r;
                int bc = 2 * kk + b_c;
                uint32_t sa = w2b + br * 128 + ((bc ^ (br & 7)) << 4);
                LDSM4(b2[nt][0], b2[nt][1], b2[nt][2], b2[nt][3], sa);
            }
#pragma unroll
            for (int mt = 0; mt < 2; mt++)
#pragma unroll
                for (int nt = 0; nt < 2; nt++)
#pragma unroll
                    for (int hf = 0; hf < 2; hf++)
                        mma16(acc[mt][nt * 2 + hf], a[mt], &b2[nt][hf * 2]);
        }
        __syncthreads();
        if (c + 2 < KIT) load_stage(c + 2, (c + 2) % NSTAGE);
    }

#pragma unroll
    for (int mt = 0; mt < 2; mt++)
#pragma unroll
        for (int nf = 0; nf < 4; nf++)
#pragma unroll
            for (int hf = 0; hf < 2; hf++) {
                int r = wm * 32 + mt * 16 + g + hf * 8;
                int i = m0 + r;
                if (i < cnt) {
                    int pos = min(start + i, NT - 1);
                    int cb  = n0 + wn * 32 + nf * 8 + tg * 2;
                    float2 o;
                    o.x = acc[mt][nf][hf * 2 + 0];
                    o.y = acc[mt][nf][hf * 2 + 1];
                    *(float2*)(out + (size_t)pos * DIMD + cb) = o;
                }
            }
}

__global__ void zero_out_kernel(float4* o, int n4) {
    int i = blockIdx.x * blockDim.x + threadIdx.x;
    if (i < n4) o[i] = make_float4(0.f, 0.f, 0.f, 0.f);
}

extern "C" void kernel_launch(void* const* d_in, const int* in_sizes, int n_in,
                              void* d_out, int out_size) {
    (void)in_sizes; (void)n_in; (void)out_size;
    const float* x    = (const float*)d_in[0];
    const int*   cnts = (const int*)d_in[1];
    const float* w1   = (const float*)d_in[2];
    const float* w2   = (const float*)d_in[3];
    const float* w3   = (const float*)d_in[4];
    float* out = (float*)d_out;

    __half *xh, *w1h, *w2h, *w3h;
    cudaGetSymbolAddress((void**)&xh,  g_xh);
    cudaGetSymbolAddress((void**)&w1h, g_w1h);
    cudaGetSymbolAddress((void**)&w2h, g_w2h);
    cudaGetSymbolAddress((void**)&w3h, g_w3h);

    cudaFuncSetAttribute(moe_up,   cudaFuncAttributeMaxDynamicSharedMemorySize, NSTAGE * 32768);
    cudaFuncSetAttribute(moe_down, cudaFuncAttributeMaxDynamicSharedMemorySize, NSTAGE * 24576);

    const int nx = NT * DIMD / 4;
    const int nw = NE * HID * DIMD / 4;
    f2h_kernel<<<592, 256>>>((const float4*)x,  (uint2*)xh,  nx);
    f2h_kernel<<<592, 256>>>((const float4*)w1, (uint2*)w1h, nw);
    f2h_kernel<<<592, 256>>>((const float4*)w2, (uint2*)w2h, nw);
    f2h_kernel<<<592, 256>>>((const float4*)w3, (uint2*)w3h, nw);

    const int n4 = NT * DIMD / 4;
    zero_out_kernel<<<(n4 + 255) / 256, 256>>>((float4*)out, n4);

    moe_up<<<dim3(CAP / BM, HID / BN, NE), THREADS, NSTAGE * 32768>>>(cnts);
    moe_down<<<dim3(CAP / BM, DIMD / BN, NE), THREADS, NSTAGE * 24576>>>(cnts, out);
}

// round 8
// speedup vs baseline: 2.8658x; 1.0471x over previous
#include <cuda_runtime.h>
#include <cuda_fp16.h>
#include <cstdint>

#define NT   8192
#define DIMD 2048
#define HID  1408
#define NE   8
#define CAP  (NT/NE)   // 1024

#define BM 128
#define BN 64
#define BK2 64         // fp16 K-elems per stage (128B rows)
#define THREADS 256
#define NSTAGE 3

// fp16 copies of inputs + fp16 intermediate h
__device__ __half g_xh[(size_t)NT * DIMD];
__device__ __half g_w1h[(size_t)NE * HID * DIMD];
__device__ __half g_w3h[(size_t)NE * HID * DIMD];
__device__ __half g_w2h[(size_t)NE * DIMD * HID];
__device__ __half g_h[(size_t)NT * HID];

__device__ __forceinline__ uint32_t smem_u32(const void* p) {
    uint32_t a;
    asm("{ .reg .u64 t; cvta.to.shared.u64 t, %1; cvt.u32.u64 %0, t; }" : "=r"(a) : "l"(p));
    return a;
}

#define CP16(s, g)   asm volatile("cp.async.cg.shared.global [%0], [%1], 16;" :: "r"(s), "l"(g))
#define CP_COMMIT()  asm volatile("cp.async.commit_group;" ::: "memory")
#define CP_WAIT1()   asm volatile("cp.async.wait_group 1;" ::: "memory")
#define CP_WAIT0()   asm volatile("cp.async.wait_group 0;" ::: "memory")

#define LDSM4(r0, r1, r2, r3, a) \
    asm volatile("ldmatrix.sync.aligned.m8n8.x4.shared.b16 {%0,%1,%2,%3}, [%4];" \
        : "=r"(r0), "=r"(r1), "=r"(r2), "=r"(r3) : "r"(a))

__device__ __forceinline__ void mma16(float* d, const uint32_t* a, const uint32_t* b) {
    asm volatile(
        "mma.sync.aligned.m16n8k16.row.col.f32.f16.f16.f32 "
        "{%0,%1,%2,%3}, {%4,%5,%6,%7}, {%8,%9}, {%0,%1,%2,%3};"
        : "+f"(d[0]), "+f"(d[1]), "+f"(d[2]), "+f"(d[3])
        : "r"(a[0]), "r"(a[1]), "r"(a[2]), "r"(a[3]), "r"(b[0]), "r"(b[1]));
}

__device__ __forceinline__ float silu(float v) { return v / (1.f + __expf(-v)); }

// ---------------------------------------------------------------------------
// fp32 -> fp16 convert (RN); single kernel, grid-stride
// ---------------------------------------------------------------------------
__device__ __forceinline__ void cvt4(const float4* s, uint2* d, int i) {
    float4 v = s[i];
    __half2 lo = __floats2half2_rn(v.x, v.y);
    __half2 hi = __floats2half2_rn(v.z, v.w);
    uint2 o;
    o.x = *(const uint32_t*)&lo;
    o.y = *(const uint32_t*)&hi;
    d[i] = o;
}

__global__ void f2h_x(const float4* __restrict__ src, uint2* __restrict__ dst, int n4) {
    int i = blockIdx.x * blockDim.x + threadIdx.x;
    int stride = gridDim.x * blockDim.x;
    for (; i < n4; i += stride) cvt4(src, dst, i);
}

// all three weight tensors in one launch (same element count each)
__global__ void f2h_w(const float4* __restrict__ s1, const float4* __restrict__ s2,
                      const float4* __restrict__ s3,
                      uint2* __restrict__ d1, uint2* __restrict__ d2, uint2* __restrict__ d3,
                      int n4) {
    int i = blockIdx.x * blockDim.x + threadIdx.x;
    int stride = gridDim.x * blockDim.x;
    for (; i < n4; i += stride) {
        cvt4(s1, d1, i);
        cvt4(s2, d2, i);
        cvt4(s3, d3, i);
    }
}

// ---------------------------------------------------------------------------
// Pass 1: h = silu(x@w1^T) * (x@w3^T)   [fp16 in, fp32 acc, fp16 h out]
// grid (CAP/BM=8, HID/BN=22, NE); smem 3 x 32KB (x 16KB | w1 8KB | w3 8KB)
// single barrier per K-step
// ---------------------------------------------------------------------------
__global__ void __launch_bounds__(THREADS, 2) moe_up(
    const int* __restrict__ cnts)
{
    extern __shared__ char smc[];
    const uint32_t sb = smem_u32(smc);
    const int tid = threadIdx.x, warp = tid >> 5, lane = tid & 31;
    const int e = blockIdx.z, m0 = blockIdx.x * BM, n0 = blockIdx.y * BN;

    int start = 0;
#pragma unroll
    for (int j = 0; j < NE; j++) { int c = cnts[j]; if (j < e) start += c; }
    const int start_cl = min(start, NT - CAP);

    const __half* xg  = g_xh  + (size_t)(start_cl + m0) * DIMD;
    const __half* w1g = g_w1h + (size_t)e * HID * DIMD + (size_t)n0 * DIMD;
    const __half* w3g = g_w3h + (size_t)e * HID * DIMD + (size_t)n0 * DIMD;

    const int wm = warp >> 1, wn = warp & 1;   // 4 m-warps x 2 n-warps
    const int g = lane >> 2, tg = lane & 3;

    float acc1[2][4][4], acc3[2][4][4];
#pragma unroll
    for (int i = 0; i < 2; i++)
#pragma unroll
        for (int j = 0; j < 4; j++)
#pragma unroll
            for (int k = 0; k < 4; k++) { acc1[i][j][k] = 0.f; acc3[i][j][k] = 0.f; }

    // stage = 256 rows x 128B; 2048 16B-chunks / 256 thr = 8 each
    auto load_stage = [&](int c, int buf) {
        const uint32_t base = sb + buf * 32768;
        const int koff = c * BK2;
#pragma unroll
        for (int j = 0; j < 8; j++) {
            int id = tid + j * THREADS;
            int row = id >> 3, k4 = id & 7;
            uint32_t sa = base + row * 128 + ((k4 ^ (row & 7)) << 4);
            const __half* gp;
            if (row < 128)      gp = xg  + (size_t)row * DIMD + koff + k4 * 8;
            else if (row < 192) gp = w1g + (size_t)(row - 128) * DIMD + koff + k4 * 8;
            else                gp = w3g + (size_t)(row - 192) * DIMD + koff + k4 * 8;
            CP16(sa, gp);
        }
        CP_COMMIT();
    };

    load_stage(0, 0);
    load_stage(1, 1);

    const int a_r = (lane & 7) + ((lane >> 3) & 1) * 8;
    const int a_c = (lane >> 4);
    const int b_r = (lane & 7) + ((lane >> 4) & 1) * 8;
    const int b_c = ((lane >> 3) & 1);

    const int KIT = DIMD / BK2;   // 32
    int s = 0, nxt = 2;
    for (int c = 0; c < KIT; c++) {
        if (c + 1 < KIT) { CP_WAIT1(); } else { CP_WAIT0(); }
        __syncthreads();
        if (c + 2 < KIT) load_stage(c + 2, nxt);
        const uint32_t xb = sb + s * 32768;
        const uint32_t w1b = xb + 16384;
        const uint32_t w3b = xb + 24576;
#pragma unroll
        for (int kk = 0; kk < 4; kk++) {
            uint32_t a[2][4], b1[2][4], b3[2][4];
#pragma unroll
            for (int mt = 0; mt < 2; mt++) {
                int lr = wm * 32 + mt * 16 + a_r;
                int lc = 2 * kk + a_c;
                uint32_t sa = xb + lr * 128 + ((lc ^ (lr & 7)) << 4);
                LDSM4(a[mt][0], a[mt][1], a[mt][2], a[mt][3], sa);
            }
#pragma unroll
            for (int nt = 0; nt < 2; nt++) {
                int br = wn * 32 + nt * 16 + b_r;
                int bc = 2 * kk + b_c;
                uint32_t sw = ((bc ^ (br & 7)) << 4);
                uint32_t s1 = w1b + br * 128 + sw;
                uint32_t s3 = w3b + br * 128 + sw;
                LDSM4(b1[nt][0], b1[nt][1], b1[nt][2], b1[nt][3], s1);
                LDSM4(b3[nt][0], b3[nt][1], b3[nt][2], b3[nt][3], s3);
            }
#pragma unroll
            for (int mt = 0; mt < 2; mt++)
#pragma unroll
                for (int nt = 0; nt < 2; nt++)
#pragma unroll
                    for (int hf = 0; hf < 2; hf++) {
                        mma16(acc1[mt][nt * 2 + hf], a[mt], &b1[nt][hf * 2]);
                        mma16(acc3[mt][nt * 2 + hf], a[mt], &b3[nt][hf * 2]);
                    }
        }
        s = (s == NSTAGE - 1) ? 0 : s + 1;
        nxt = (nxt == NSTAGE - 1) ? 0 : nxt + 1;
    }

    // Epilogue: h = fp16(silu(a1) * a3)
    __half* hg = g_h + (size_t)(e * CAP + m0) * HID + n0;
#pragma unroll
    for (int mt = 0; mt < 2; mt++)
#pragma unroll
        for (int nf = 0; nf < 4; nf++)
#pragma unroll
            for (int hf = 0; hf < 2; hf++) {
                int r  = wm * 32 + mt * 16 + g + hf * 8;
                int cb = wn * 32 + nf * 8 + tg * 2;
                float v1a = acc1[mt][nf][hf * 2 + 0];
                float v1b = acc1[mt][nf][hf * 2 + 1];
                float v3a = acc3[mt][nf][hf * 2 + 0];
                float v3b = acc3[mt][nf][hf * 2 + 1];
                __half2 o = __floats2half2_rn(silu(v1a) * v3a, silu(v1b) * v3b);
                *(uint32_t*)(hg + (size_t)r * HID + cb) = *(const uint32_t*)&o;
            }
}

// ---------------------------------------------------------------------------
// Pass 2: out = h @ w2^T (fp32 out, masked scatter)
// grid (CAP/BM=8, DIMD/BN=32, NE); smem 3 x 24KB (h 16KB | w2 8KB)
// ---------------------------------------------------------------------------
__global__ void __launch_bounds__(THREADS, 2) moe_down(
    const int* __restrict__ cnts, float* __restrict__ out)
{
    extern __shared__ char smc[];
    const uint32_t sb = smem_u32(smc);
    const int tid = threadIdx.x, warp = tid >> 5, lane = tid & 31;
    const int e = blockIdx.z, m0 = blockIdx.x * BM, n0 = blockIdx.y * BN;

    int start = 0, cnt = 0;
#pragma unroll
    for (int j = 0; j < NE; j++) {
        int c = cnts[j];
        if (j < e) start += c;
        if (j == e) cnt = c;
    }

    const __half* hg  = g_h   + (size_t)(e * CAP + m0) * HID;
    const __half* w2g = g_w2h + (size_t)e * DIMD * HID + (size_t)n0 * HID;

    const int wm = warp >> 1, wn = warp & 1;
    const int g = lane >> 2, tg = lane & 3;

    float acc[2][4][4];
#pragma unroll
    for (int i = 0; i < 2; i++)
#pragma unroll
        for (int j = 0; j < 4; j++)
#pragma unroll
            for (int k = 0; k < 4; k++) acc[i][j][k] = 0.f;

    auto load_stage = [&](int c, int buf) {
        const uint32_t base = sb + buf * 24576;
        const int koff = c * BK2;
#pragma unroll
        for (int j = 0; j < 6; j++) {
            int id = tid + j * THREADS;
            int row = id >> 3, k4 = id & 7;
            uint32_t sa = base + row * 128 + ((k4 ^ (row & 7)) << 4);
            const __half* gp;
            if (row < 128) gp = hg  + (size_t)row * HID + koff + k4 * 8;
            else           gp = w2g + (size_t)(row - 128) * HID + koff + k4 * 8;
            CP16(sa, gp);
        }
        CP_COMMIT();
    };

    load_stage(0, 0);
    load_stage(1, 1);

    const int a_r = (lane & 7) + ((lane >> 3) & 1) * 8;
    const int a_c = (lane >> 4);
    const int b_r = (lane & 7) + ((lane >> 4) & 1) * 8;
    const int b_c = ((lane >> 3) & 1);

    const int KIT = HID / BK2;   // 22
    int s = 0, nxt = 2;
    for (int c = 0; c < KIT; c++) {
        if (c + 1 < KIT) { CP_WAIT1(); } else { CP_WAIT0(); }
        __syncthreads();
        if (c + 2 < KIT) load_stage(c + 2, nxt);
        const uint32_t xb = sb + s * 24576;
        const uint32_t w2b = xb + 16384;
#pragma unroll
        for (int kk = 0; kk < 4; kk++) {
            uint32_t a[2][4], b2[2][4];
#pragma unroll
            for (int mt = 0; mt < 2; mt++) {
                int lr = wm * 32 + mt * 16 + a_r;
                int lc = 2 * kk + a_c;
                uint32_t sa = xb + lr * 128 + ((lc ^ (lr & 7)) << 4);
                LDSM4(a[mt][0], a[mt][1], a[mt][2], a[mt][3], sa);
            }
#pragma unroll
            for (int nt = 0; nt < 2; nt++) {
                int br = wn * 32 + nt * 16 + b_r;
                int bc = 2 * kk + b_c;
                uint32_t sa = w2b + br * 128 + ((bc ^ (br & 7)) << 4);
                LDSM4(b2[nt][0], b2[nt][1], b2[nt][2], b2[nt][3], sa);
            }
#pragma unroll
            for (int mt = 0; mt < 2; mt++)
#pragma unroll
                for (int nt = 0; nt < 2; nt++)
#pragma unroll
                    for (int hf = 0; hf < 2; hf++)
                        mma16(acc[mt][nt * 2 + hf], a[mt], &b2[nt][hf * 2]);
        }
        s = (s == NSTAGE - 1) ? 0 : s + 1;
        nxt = (nxt == NSTAGE - 1) ? 0 : nxt + 1;
    }

#pragma unroll
    for (int mt = 0; mt < 2; mt++)
#pragma unroll
        for (int nf = 0; nf < 4; nf++)
#pragma unroll
            for (int hf = 0; hf < 2; hf++) {
                int r = wm * 32 + mt * 16 + g + hf * 8;
                int i = m0 + r;
                if (i < cnt) {
                    int pos = min(start + i, NT - 1);
                    int cb  = n0 + wn * 32 + nf * 8 + tg * 2;
                    float2 o;
                    o.x = acc[mt][nf][hf * 2 + 0];
                    o.y = acc[mt][nf][hf * 2 + 1];
                    *(float2*)(out + (size_t)pos * DIMD + cb) = o;
                }
            }
}

extern "C" void kernel_launch(void* const* d_in, const int* in_sizes, int n_in,
                              void* d_out, int out_size) {
    (void)in_sizes; (void)n_in; (void)out_size;
    const float* x    = (const float*)d_in[0];
    const int*   cnts = (const int*)d_in[1];
    const float* w1   = (const float*)d_in[2];
    const float* w2   = (const float*)d_in[3];
    const float* w3   = (const float*)d_in[4];
    float* out = (float*)d_out;

    __half *xh, *w1h, *w2h, *w3h;
    cudaGetSymbolAddress((void**)&xh,  g_xh);
    cudaGetSymbolAddress((void**)&w1h, g_w1h);
    cudaGetSymbolAddress((void**)&w2h, g_w2h);
    cudaGetSymbolAddress((void**)&w3h, g_w3h);

    cudaFuncSetAttribute(moe_up,   cudaFuncAttributeMaxDynamicSharedMemorySize, NSTAGE * 32768);
    cudaFuncSetAttribute(moe_down, cudaFuncAttributeMaxDynamicSharedMemorySize, NSTAGE * 24576);

    const int nx = NT * DIMD / 4;
    const int nw = NE * HID * DIMD / 4;
    f2h_x<<<592, 256>>>((const float4*)x, (uint2*)xh, nx);
    f2h_w<<<592, 256>>>((const float4*)w1, (const float4*)w2, (const float4*)w3,
                        (uint2*)w1h, (uint2*)w2h, (uint2*)w3h, nw);

    moe_up<<<dim3(CAP / BM, HID / BN, NE), THREADS, NSTAGE * 32768>>>(cnts);
    moe_down<<<dim3(CAP / BM, DIMD / BN, NE), THREADS, NSTAGE * 24576>>>(cnts, out);
}